// round 13
// baseline (speedup 1.0000x reference)
#include <cuda_runtime.h>
#include <cuda_fp16.h>
#include <cstdint>

#define EXP    8
#define DIN    2048
#define DOUT   2048
#define NTOK   4096
#define KROUTE 2
#define MTOT   (NTOK * KROUTE)

#define TM 128
#define TN 128
#define TK 64
#define KB (DIN / TK)             // 32
#define NSTG 3
#define LDSS 72                   // padded smem row stride in fp16 elems (144B)
#define TILEB (TM * LDSS * 2)     // 18432 bytes per tile
#define STGB  (2 * TILEB)         // X, W per stage = 36864

#define WEFF_BLOCKS (EXP * 32 * 32)          // 8192
#define PREPX_BLOCKS ((NTOK * DIN) / 1024)   // 8192

// ---- scratch (device globals; no runtime allocation allowed) ----
__device__ __half g_w[(size_t)EXP * DOUT * DIN];
__device__ __half g_x[(size_t)NTOK * DIN];

// ---------------- PTX helpers ----------------
__device__ __forceinline__ void cpa16(uint32_t dst, const void* src, int bytes) {
    asm volatile("cp.async.cg.shared.global [%0], [%1], 16, %2;\n"
                 :: "r"(dst), "l"(src), "r"(bytes));
}
__device__ __forceinline__ void cp_commit() { asm volatile("cp.async.commit_group;\n"); }

__device__ __forceinline__ void ldm4(uint32_t* r, uint32_t a) {
    asm volatile("ldmatrix.sync.aligned.m8n8.x4.shared.b16 {%0,%1,%2,%3}, [%4];\n"
                 : "=r"(r[0]), "=r"(r[1]), "=r"(r[2]), "=r"(r[3]) : "r"(a));
}
__device__ __forceinline__ void mma16816(float* c, const uint32_t* a, uint32_t b0, uint32_t b1) {
    asm volatile("mma.sync.aligned.m16n8k16.row.col.f32.f16.f16.f32 "
                 "{%0,%1,%2,%3}, {%4,%5,%6,%7}, {%8,%9}, {%0,%1,%2,%3};\n"
                 : "+f"(c[0]), "+f"(c[1]), "+f"(c[2]), "+f"(c[3])
                 : "r"(a[0]), "r"(a[1]), "r"(a[2]), "r"(a[3]), "r"(b0), "r"(b1));
}
__device__ __forceinline__ void red2(float* p, float v0, float v1) {
    asm volatile("red.global.add.v2.f32 [%0], {%1,%2};\n" :: "l"(p), "f"(v0), "f"(v1) : "memory");
}

// ---------------- fused prep: blocks [0,8192) = W_eff; [8192,16384) = x + zero out ----------------
__global__ void __launch_bounds__(256) prep_all_kernel(
    const float* __restrict__ weight, const float* __restrict__ lA,
    const float* __restrict__ lB, const float* __restrict__ x,
    float* __restrict__ out)
{
    const int t = threadIdx.x;

    if (blockIdx.x >= WEFF_BLOCKS) {
        size_t i = ((size_t)(blockIdx.x - WEFF_BLOCKS) * 256 + t) * 4;
        float4 v = *reinterpret_cast<const float4*>(x + i);
        reinterpret_cast<__half2*>(g_x + i)[0] =
            __halves2half2(__float2half_rn(v.x), __float2half_rn(v.y));
        reinterpret_cast<__half2*>(g_x + i)[1] =
            __halves2half2(__float2half_rn(v.z), __float2half_rn(v.w));
        *reinterpret_cast<float4*>(out + i) = make_float4(0.f, 0.f, 0.f, 0.f);
        return;
    }

    __shared__ float Bs[64][16];
    __shared__ __align__(16) float As[16][68];
    const int b = blockIdx.x;
    const int e = b >> 10;
    const int jt = (b >> 5) & 31;
    const int dt = b & 31;
    const int j0 = jt * 64, d0 = dt * 64;
    {
        int jj = t >> 2, q = t & 3;
        float4 v = *reinterpret_cast<const float4*>(lB + ((size_t)e * DOUT + j0 + jj) * 16 + q * 4);
        Bs[jj][q * 4 + 0] = v.x; Bs[jj][q * 4 + 1] = v.y;
        Bs[jj][q * 4 + 2] = v.z; Bs[jj][q * 4 + 3] = v.w;
    }
    {
        int r = t >> 4, dd = (t & 15) * 4;
        float4 v = *reinterpret_cast<const float4*>(lA + ((size_t)e * 16 + r) * DIN + d0 + dd);
        *reinterpret_cast<float4*>(&As[r][dd]) = v;
    }
    __syncthreads();
    const int tj = t >> 4, td = t & 15;

    float4 w[4];
    size_t base0 = ((size_t)e * DOUT + j0 + tj * 4) * DIN + d0 + td * 4;
    #pragma unroll
    for (int a = 0; a < 4; a++)
        w[a] = *reinterpret_cast<const float4*>(weight + base0 + (size_t)a * DIN);

    float dw[4][4];
    #pragma unroll
    for (int a = 0; a < 4; a++)
        #pragma unroll
        for (int q = 0; q < 4; q++) dw[a][q] = 0.f;

    #pragma unroll
    for (int r = 0; r < 16; r++) {
        float4 a4 = *reinterpret_cast<const float4*>(&As[r][td * 4]);
        #pragma unroll
        for (int a = 0; a < 4; a++) {
            float bb = Bs[tj * 4 + a][r];
            dw[a][0] += bb * a4.x;
            dw[a][1] += bb * a4.y;
            dw[a][2] += bb * a4.z;
            dw[a][3] += bb * a4.w;
        }
    }

    #pragma unroll
    for (int a = 0; a < 4; a++) {
        size_t base = base0 + (size_t)a * DIN;
        __half h0 = __float2half_rn(w[a].x + 2.0f * dw[a][0]);
        __half h1 = __float2half_rn(w[a].y + 2.0f * dw[a][1]);
        __half h2 = __float2half_rn(w[a].z + 2.0f * dw[a][2]);
        __half h3 = __float2half_rn(w[a].w + 2.0f * dw[a][3]);
        reinterpret_cast<__half2*>(g_w + base)[0] = __halves2half2(h0, h1);
        reinterpret_cast<__half2*>(g_w + base)[1] = __halves2half2(h2, h3);
    }
}

// ---------------- grouped GEMM (fp16, mma.sync, TK=64, 3-stage, 256 thr, 64x32 warp tile,
//                  2 CTA/SM, ks-level fragment double-buffering) ----------------
__global__ void __launch_bounds__(256, 2) moe_gemm(
    const int* __restrict__ ssi, const int* __restrict__ eoff,
    const float* __restrict__ gates, float* __restrict__ out)
{
    extern __shared__ __align__(256) char smem[];
    uint32_t sb = (uint32_t)__cvta_generic_to_shared(smem);
    int*   tok_s  = reinterpret_cast<int*>(smem);
    float* gate_s = reinterpret_cast<float*>(smem + TM * 4);
    const uint32_t sbuf = sb + 1024;

    const int n0 = blockIdx.x * TN;   // n fastest -> x rows L2-resident across n
    const int mt = blockIdx.y;

    int expert = -1, m0 = 0, mcnt = 0;
    {
        int prev = 0, acc_t = 0;
        #pragma unroll
        for (int e = 0; e < EXP; e++) {
            int end = eoff[e];
            int cnt = end - prev;
            int tiles = (cnt + TM - 1) / TM;
            if (expert < 0 && mt >= acc_t && mt < acc_t + tiles) {
                expert = e;
                m0 = prev + (mt - acc_t) * TM;
                mcnt = end - m0;
                if (mcnt > TM) mcnt = TM;
            }
            acc_t += tiles;
            prev = end;
        }
    }
    if (expert < 0) return;

    const int tid  = threadIdx.x;
    const int lane = tid & 31;
    const int warp = tid >> 5;
    const int wm   = warp & 1;    // 0..1 : 64-row slice
    const int wn   = warp >> 1;   // 0..3 : 32-col slice

    if (tid < TM) {
        int tok = -1; float g = 0.f;
        if (tid < mcnt) {
            int s = ssi[m0 + tid];
            tok = s / KROUTE;
            int slot = s - tok * KROUTE;
            g = gates[tok * KROUTE + slot];
        }
        tok_s[tid]  = tok;
        gate_s[tid] = g;
    }
    __syncthreads();

    float acc[4][4][4];
    #pragma unroll
    for (int i = 0; i < 4; i++)
        #pragma unroll
        for (int j = 0; j < 4; j++)
            #pragma unroll
            for (int q = 0; q < 4; q++) acc[i][j][q] = 0.f;

    const size_t wbase = (size_t)expert * DOUT * DIN;

    // per-thread smem base offsets (constant across kb; ks/mi/nq offsets are immediates)
    const uint32_t aOffBase = (uint32_t)((wm * 64 + (lane & 15)) * LDSS + (lane >> 4) * 8) * 2;
    const uint32_t bOffBase = (uint32_t)((wn * 32 + (lane & 7) + ((lane >> 4) << 3)) * LDSS
                                         + ((lane >> 3) & 1) * 8) * 2;

    auto load_stage = [&](int buf, int kb) {
        const int k0 = kb * TK;
        const uint32_t s = sbuf + (uint32_t)buf * STGB;
        #pragma unroll
        for (int it = 0; it < 4; it++) {
            int idx = tid + it * 256;         // 0..1023
            int row = idx >> 3, c = idx & 7;  // 8 chunks of 16B per 128B row
            uint32_t soff = (uint32_t)(row * (LDSS * 2) + c * 16);
            int tok = tok_s[row];
            size_t xoff = (size_t)(tok < 0 ? 0 : tok) * DIN + k0 + c * 8;
            int bytes = (tok < 0) ? 0 : 16;
            cpa16(s + soff, g_x + xoff, bytes);
            size_t woff = wbase + (size_t)(n0 + row) * DIN + k0 + c * 8;
            cpa16(s + TILEB + soff, g_w + woff, 16);
        }
        cp_commit();
    };

    load_stage(0, 0);
    load_stage(1, 1);

    int buf = 0;
    for (int kb = 0; kb < KB; kb++) {
        asm volatile("cp.async.wait_group 1;\n");
        __syncthreads();
        if (kb + 2 < KB) {
            int nb = buf + 2; if (nb >= NSTG) nb -= NSTG;
            load_stage(nb, kb + 2);
        } else {
            cp_commit();   // keep group-count invariant
        }

        const uint32_t aX = sbuf + (uint32_t)buf * STGB + aOffBase;
        const uint32_t bW = sbuf + (uint32_t)buf * STGB + TILEB + bOffBase;

        // double-buffered fragments across the 4 ks-groups
        uint32_t axP[4][4], bwP[2][4];   // ping
        uint32_t axQ[4][4], bwQ[2][4];   // pong
        {   // prologue: load ks=0 into ping
            #pragma unroll
            for (int mi = 0; mi < 4; mi++) ldm4(axP[mi], aX + (uint32_t)(mi * 16 * LDSS * 2));
            #pragma unroll
            for (int nq = 0; nq < 2; nq++) ldm4(bwP[nq], bW + (uint32_t)(nq * 16 * LDSS * 2));
        }

        #pragma unroll
        for (int ks = 0; ks < 4; ks++) {
            uint32_t (*axC)[4] = (ks & 1) ? axQ : axP;
            uint32_t (*bwC)[4] = (ks & 1) ? bwQ : bwP;
            uint32_t (*axN)[4] = (ks & 1) ? axP : axQ;
            uint32_t (*bwN)[4] = (ks & 1) ? bwP : bwQ;

            if (ks < 3) {   // prefetch ks+1 fragments before issuing HMMAs
                uint32_t ko = (uint32_t)((ks + 1) * 32);
                #pragma unroll
                for (int nq = 0; nq < 2; nq++)
                    ldm4(bwN[nq], bW + ko + (uint32_t)(nq * 16 * LDSS * 2));
                #pragma unroll
                for (int mi = 0; mi < 4; mi++)
                    ldm4(axN[mi], aX + ko + (uint32_t)(mi * 16 * LDSS * 2));
            }

            #pragma unroll
            for (int ni = 0; ni < 4; ni++) {
                uint32_t b0 = bwC[ni >> 1][(ni & 1) * 2 + 0];
                uint32_t b1 = bwC[ni >> 1][(ni & 1) * 2 + 1];
                #pragma unroll
                for (int mi = 0; mi < 4; mi++) {
                    mma16816(acc[mi][ni], axC[mi], b0, b1);
                }
            }
        }
        buf = (buf + 1 == NSTG) ? 0 : buf + 1;
    }

    // epilogue: gate + scatter red.add (k=2 routes collide per token)
    const int g = lane >> 2, tg = lane & 3;
    #pragma unroll
    for (int mi = 0; mi < 4; mi++) {
        #pragma unroll
        for (int half = 0; half < 2; half++) {
            int mr = wm * 64 + mi * 16 + g + half * 8;
            int tok = tok_s[mr];
            if (tok < 0) continue;
            float gg = gate_s[mr];
            float* orow = out + (size_t)tok * DOUT + n0 + wn * 32 + tg * 2;
            #pragma unroll
            for (int ni = 0; ni < 4; ni++) {
                red2(orow + ni * 8,
                     acc[mi][ni][half * 2 + 0] * gg,
                     acc[mi][ni][half * 2 + 1] * gg);
            }
        }
    }
}

// ---------------- launch ----------------
extern "C" void kernel_launch(void* const* d_in, const int* in_sizes, int n_in,
                              void* d_out, int out_size) {
    const float* inputs = (const float*)d_in[0];
    const float* weight = (const float*)d_in[1];
    const float* lora_A = (const float*)d_in[2];
    const float* lora_B = (const float*)d_in[3];
    const float* gates  = (const float*)d_in[4];
    const int*   ssi    = (const int*)d_in[6];
    const int*   eoff   = (const int*)d_in[7];
    float* out = (float*)d_out;

    const int SMEM_BYTES = 1024 + NSTG * STGB;   // 1024 + 110592 = 111616
    cudaFuncSetAttribute(moe_gemm, cudaFuncAttributeMaxDynamicSharedMemorySize, SMEM_BYTES);

    prep_all_kernel<<<WEFF_BLOCKS + PREPX_BLOCKS, 256>>>(weight, lora_A, lora_B, inputs, out);

    dim3 grid(DOUT / TN, MTOT / TM + EXP);   // 16 x 72
    moe_gemm<<<grid, 256, SMEM_BYTES>>>(ssi, eoff, gates, out);
}

// round 14
// speedup vs baseline: 1.0370x; 1.0370x over previous
#include <cuda_runtime.h>
#include <cuda_fp16.h>
#include <cstdint>

#define EXP    8
#define DIN    2048
#define DOUT   2048
#define NTOK   4096
#define KROUTE 2
#define MTOT   (NTOK * KROUTE)

#define TM 128
#define TN 128
#define TK 64
#define KB (DIN / TK)             // 32
#define NSTG 3
#define LDSS 72                   // padded smem row stride in fp16 elems (144B)
#define TILEB (TM * LDSS * 2)     // 18432 bytes per tile
#define STGB  (2 * TILEB)         // X, W per stage = 36864

#define WEFF_BLOCKS (EXP * 32 * 32)          // 8192
#define PREPX_BLOCKS ((NTOK * DIN) / 1024)   // 8192

// ---- scratch (device globals; no runtime allocation allowed) ----
__device__ __half g_w[(size_t)EXP * DOUT * DIN];
__device__ __half g_x[(size_t)NTOK * DIN];

// ---------------- PTX helpers ----------------
__device__ __forceinline__ void cpa16(uint32_t dst, const void* src, int bytes) {
    asm volatile("cp.async.cg.shared.global [%0], [%1], 16, %2;\n"
                 :: "r"(dst), "l"(src), "r"(bytes));
}
__device__ __forceinline__ void cp_commit() { asm volatile("cp.async.commit_group;\n"); }

__device__ __forceinline__ void ldm4(uint32_t* r, uint32_t a) {
    asm volatile("ldmatrix.sync.aligned.m8n8.x4.shared.b16 {%0,%1,%2,%3}, [%4];\n"
                 : "=r"(r[0]), "=r"(r[1]), "=r"(r[2]), "=r"(r[3]) : "r"(a));
}
__device__ __forceinline__ void mma16816(float* c, const uint32_t* a, uint32_t b0, uint32_t b1) {
    asm volatile("mma.sync.aligned.m16n8k16.row.col.f32.f16.f16.f32 "
                 "{%0,%1,%2,%3}, {%4,%5,%6,%7}, {%8,%9}, {%0,%1,%2,%3};\n"
                 : "+f"(c[0]), "+f"(c[1]), "+f"(c[2]), "+f"(c[3])
                 : "r"(a[0]), "r"(a[1]), "r"(a[2]), "r"(a[3]), "r"(b0), "r"(b1));
}
__device__ __forceinline__ void red2(float* p, float v0, float v1) {
    asm volatile("red.global.add.v2.f32 [%0], {%1,%2};\n" :: "l"(p), "f"(v0), "f"(v1) : "memory");
}

// ---------------- fused prep: blocks [0,8192) = W_eff; [8192,16384) = x + zero out ----------------
// launch_bounds(256, 5): force <=51 regs -> 5 CTAs/SM (occ 62%) to cover DRAM/LDS latency
__global__ void __launch_bounds__(256, 5) prep_all_kernel(
    const float* __restrict__ weight, const float* __restrict__ lA,
    const float* __restrict__ lB, const float* __restrict__ x,
    float* __restrict__ out)
{
    const int t = threadIdx.x;

    if (blockIdx.x >= WEFF_BLOCKS) {
        size_t i = ((size_t)(blockIdx.x - WEFF_BLOCKS) * 256 + t) * 4;
        float4 v = *reinterpret_cast<const float4*>(x + i);
        reinterpret_cast<__half2*>(g_x + i)[0] =
            __halves2half2(__float2half_rn(v.x), __float2half_rn(v.y));
        reinterpret_cast<__half2*>(g_x + i)[1] =
            __halves2half2(__float2half_rn(v.z), __float2half_rn(v.w));
        *reinterpret_cast<float4*>(out + i) = make_float4(0.f, 0.f, 0.f, 0.f);
        return;
    }

    __shared__ float Bs[64][16];
    __shared__ __align__(16) float As[16][68];
    const int b = blockIdx.x;
    const int e = b >> 10;
    const int jt = (b >> 5) & 31;
    const int dt = b & 31;
    const int j0 = jt * 64, d0 = dt * 64;
    {
        int jj = t >> 2, q = t & 3;
        float4 v = *reinterpret_cast<const float4*>(lB + ((size_t)e * DOUT + j0 + jj) * 16 + q * 4);
        Bs[jj][q * 4 + 0] = v.x; Bs[jj][q * 4 + 1] = v.y;
        Bs[jj][q * 4 + 2] = v.z; Bs[jj][q * 4 + 3] = v.w;
    }
    {
        int r = t >> 4, dd = (t & 15) * 4;
        float4 v = *reinterpret_cast<const float4*>(lA + ((size_t)e * 16 + r) * DIN + d0 + dd);
        *reinterpret_cast<float4*>(&As[r][dd]) = v;
    }
    __syncthreads();
    const int tj = t >> 4, td = t & 15;

    // 16 independent FMA chains: dw[a][0..3]  (W loaded after, per-row, to fit 51 regs)
    float dw[4][4];
    #pragma unroll
    for (int a = 0; a < 4; a++)
        #pragma unroll
        for (int q = 0; q < 4; q++) dw[a][q] = 0.f;

    #pragma unroll
    for (int r = 0; r < 16; r++) {
        float4 a4 = *reinterpret_cast<const float4*>(&As[r][td * 4]);
        #pragma unroll
        for (int a = 0; a < 4; a++) {
            float bb = Bs[tj * 4 + a][r];
            dw[a][0] += bb * a4.x;
            dw[a][1] += bb * a4.y;
            dw[a][2] += bb * a4.z;
            dw[a][3] += bb * a4.w;
        }
    }

    size_t base0 = ((size_t)e * DOUT + j0 + tj * 4) * DIN + d0 + td * 4;
    #pragma unroll
    for (int a = 0; a < 4; a++) {
        size_t base = base0 + (size_t)a * DIN;
        float4 w = *reinterpret_cast<const float4*>(weight + base);
        __half h0 = __float2half_rn(w.x + 2.0f * dw[a][0]);
        __half h1 = __float2half_rn(w.y + 2.0f * dw[a][1]);
        __half h2 = __float2half_rn(w.z + 2.0f * dw[a][2]);
        __half h3 = __float2half_rn(w.w + 2.0f * dw[a][3]);
        reinterpret_cast<__half2*>(g_w + base)[0] = __halves2half2(h0, h1);
        reinterpret_cast<__half2*>(g_w + base)[1] = __halves2half2(h2, h3);
    }
}

// ---------------- grouped GEMM (fp16, mma.sync, TK=64, 3-stage, 256 thr, 64x32 warp tile, 2 CTA/SM) ----------------
__global__ void __launch_bounds__(256, 2) moe_gemm(
    const int* __restrict__ ssi, const int* __restrict__ eoff,
    const float* __restrict__ gates, float* __restrict__ out)
{
    extern __shared__ __align__(256) char smem[];
    uint32_t sb = (uint32_t)__cvta_generic_to_shared(smem);
    int*   tok_s  = reinterpret_cast<int*>(smem);
    float* gate_s = reinterpret_cast<float*>(smem + TM * 4);
    const uint32_t sbuf = sb + 1024;

    const int n0 = blockIdx.x * TN;   // n fastest -> x rows L2-resident across n
    const int mt = blockIdx.y;

    int expert = -1, m0 = 0, mcnt = 0;
    {
        int prev = 0, acc_t = 0;
        #pragma unroll
        for (int e = 0; e < EXP; e++) {
            int end = eoff[e];
            int cnt = end - prev;
            int tiles = (cnt + TM - 1) / TM;
            if (expert < 0 && mt >= acc_t && mt < acc_t + tiles) {
                expert = e;
                m0 = prev + (mt - acc_t) * TM;
                mcnt = end - m0;
                if (mcnt > TM) mcnt = TM;
            }
            acc_t += tiles;
            prev = end;
        }
    }
    if (expert < 0) return;

    const int tid  = threadIdx.x;
    const int lane = tid & 31;
    const int warp = tid >> 5;
    const int wm   = warp & 1;    // 0..1 : 64-row slice
    const int wn   = warp >> 1;   // 0..3 : 32-col slice

    if (tid < TM) {
        int tok = -1; float g = 0.f;
        if (tid < mcnt) {
            int s = ssi[m0 + tid];
            tok = s / KROUTE;
            int slot = s - tok * KROUTE;
            g = gates[tok * KROUTE + slot];
        }
        tok_s[tid]  = tok;
        gate_s[tid] = g;
    }
    __syncthreads();

    float acc[4][4][4];
    #pragma unroll
    for (int i = 0; i < 4; i++)
        #pragma unroll
        for (int j = 0; j < 4; j++)
            #pragma unroll
            for (int q = 0; q < 4; q++) acc[i][j][q] = 0.f;

    const size_t wbase = (size_t)expert * DOUT * DIN;

    auto load_stage = [&](int buf, int kb) {
        const int k0 = kb * TK;
        const uint32_t s = sbuf + (uint32_t)buf * STGB;
        #pragma unroll
        for (int it = 0; it < 4; it++) {
            int idx = tid + it * 256;         // 0..1023
            int row = idx >> 3, c = idx & 7;  // 8 chunks of 16B per 128B row
            uint32_t soff = (uint32_t)(row * (LDSS * 2) + c * 16);
            int tok = tok_s[row];
            size_t xoff = (size_t)(tok < 0 ? 0 : tok) * DIN + k0 + c * 8;
            int bytes = (tok < 0) ? 0 : 16;
            cpa16(s + soff, g_x + xoff, bytes);
            size_t woff = wbase + (size_t)(n0 + row) * DIN + k0 + c * 8;
            cpa16(s + TILEB + soff, g_w + woff, 16);
        }
        cp_commit();
    };

    load_stage(0, 0);
    load_stage(1, 1);

    int buf = 0;
    for (int kb = 0; kb < KB; kb++) {
        asm volatile("cp.async.wait_group 1;\n");
        __syncthreads();
        if (kb + 2 < KB) {
            int nb = buf + 2; if (nb >= NSTG) nb -= NSTG;
            load_stage(nb, kb + 2);
        } else {
            cp_commit();   // keep group-count invariant
        }

        const uint32_t aX = sbuf + (uint32_t)buf * STGB;
        const uint32_t bW = aX + TILEB;

        #pragma unroll
        for (int ks = 0; ks < 4; ks++) {
            uint32_t ax[4][4], bw[2][4];
            int arow = wm * 64 + (lane & 15);
            int acol = ks * 16 + (lane >> 4) * 8;
            #pragma unroll
            for (int mi = 0; mi < 4; mi++) {
                uint32_t off = (uint32_t)((arow + mi * 16) * LDSS + acol) * 2;
                ldm4(ax[mi], aX + off);
            }
            int brow = wn * 32 + (lane & 7) + ((lane >> 4) << 3);
            int bcol = ks * 16 + ((lane >> 3) & 1) * 8;
            #pragma unroll
            for (int nq = 0; nq < 2; nq++) {
                uint32_t off = (uint32_t)((brow + nq * 16) * LDSS + bcol) * 2;
                ldm4(bw[nq], bW + off);
            }
            #pragma unroll
            for (int ni = 0; ni < 4; ni++) {
                uint32_t b0 = bw[ni >> 1][(ni & 1) * 2 + 0];
                uint32_t b1 = bw[ni >> 1][(ni & 1) * 2 + 1];
                #pragma unroll
                for (int mi = 0; mi < 4; mi++) {
                    mma16816(acc[mi][ni], ax[mi], b0, b1);
                }
            }
        }
        buf = (buf + 1 == NSTG) ? 0 : buf + 1;
    }

    // epilogue: gate + scatter red.add (k=2 routes collide per token)
    const int g = lane >> 2, tg = lane & 3;
    #pragma unroll
    for (int mi = 0; mi < 4; mi++) {
        #pragma unroll
        for (int half = 0; half < 2; half++) {
            int mr = wm * 64 + mi * 16 + g + half * 8;
            int tok = tok_s[mr];
            if (tok < 0) continue;
            float gg = gate_s[mr];
            float* orow = out + (size_t)tok * DOUT + n0 + wn * 32 + tg * 2;
            #pragma unroll
            for (int ni = 0; ni < 4; ni++) {
                red2(orow + ni * 8,
                     acc[mi][ni][half * 2 + 0] * gg,
                     acc[mi][ni][half * 2 + 1] * gg);
            }
        }
    }
}

// ---------------- launch ----------------
extern "C" void kernel_launch(void* const* d_in, const int* in_sizes, int n_in,
                              void* d_out, int out_size) {
    const float* inputs = (const float*)d_in[0];
    const float* weight = (const float*)d_in[1];
    const float* lora_A = (const float*)d_in[2];
    const float* lora_B = (const float*)d_in[3];
    const float* gates  = (const float*)d_in[4];
    const int*   ssi    = (const int*)d_in[6];
    const int*   eoff   = (const int*)d_in[7];
    float* out = (float*)d_out;

    const int SMEM_BYTES = 1024 + NSTG * STGB;   // 1024 + 110592 = 111616
    cudaFuncSetAttribute(moe_gemm, cudaFuncAttributeMaxDynamicSharedMemorySize, SMEM_BYTES);

    prep_all_kernel<<<WEFF_BLOCKS + PREPX_BLOCKS, 256>>>(weight, lora_A, lora_B, inputs, out);

    dim3 grid(DOUT / TN, MTOT / TM + EXP);   // 16 x 72
    moe_gemm<<<grid, 256, SMEM_BYTES>>>(ssi, eoff, gates, out);
}